// round 1
// baseline (speedup 1.0000x reference)
#include <cuda_runtime.h>

// Submanifold 3x3 conv (cross-correlation, SAME padding) on independent 4x4x1
// tiles, output masked to sites where the input is nonzero.
// y[t,i,j] = (x[t,i,j] != 0) ? sum_{p,q in 0..2} x[t, i+p-1, j+q-1] * W[p,q] : 0
// (out-of-tile taps are zero). Output layout == input layout ([N,4,4] contiguous).

__global__ __launch_bounds__(256) void subm_conv_tile_kernel(
    const float* __restrict__ x,
    const float* __restrict__ W,
    float* __restrict__ y,
    int n_tiles)
{
    __shared__ float sw[9];
    if (threadIdx.x < 9) sw[threadIdx.x] = W[threadIdx.x];
    __syncthreads();

    int tile = blockIdx.x * blockDim.x + threadIdx.x;
    if (tile >= n_tiles) return;

    // Load 16 contiguous floats (64B, 16B-aligned) as 4x float4.
    const float4* xin = reinterpret_cast<const float4*>(x) + (size_t)tile * 4;
    float4 r0 = xin[0];
    float4 r1 = xin[1];
    float4 r2 = xin[2];
    float4 r3 = xin[3];

    // Zero-padded 6x6 input in registers; pad entries are compile-time zeros
    // so their FMAs fold away.
    float p[6][6];
#pragma unroll
    for (int i = 0; i < 6; i++)
#pragma unroll
        for (int j = 0; j < 6; j++)
            p[i][j] = 0.0f;

    p[1][1] = r0.x; p[1][2] = r0.y; p[1][3] = r0.z; p[1][4] = r0.w;
    p[2][1] = r1.x; p[2][2] = r1.y; p[2][3] = r1.z; p[2][4] = r1.w;
    p[3][1] = r2.x; p[3][2] = r2.y; p[3][3] = r2.z; p[3][4] = r2.w;
    p[4][1] = r3.x; p[4][2] = r3.y; p[4][3] = r3.z; p[4][4] = r3.w;

    float w00 = sw[0], w01 = sw[1], w02 = sw[2];
    float w10 = sw[3], w11 = sw[4], w12 = sw[5];
    float w20 = sw[6], w21 = sw[7], w22 = sw[8];

    float o[4][4];
#pragma unroll
    for (int i = 0; i < 4; i++) {
#pragma unroll
        for (int j = 0; j < 4; j++) {
            float s = 0.0f;
            s += p[i + 0][j + 0] * w00;
            s += p[i + 0][j + 1] * w01;
            s += p[i + 0][j + 2] * w02;
            s += p[i + 1][j + 0] * w10;
            s += p[i + 1][j + 1] * w11;
            s += p[i + 1][j + 2] * w12;
            s += p[i + 2][j + 0] * w20;
            s += p[i + 2][j + 1] * w21;
            s += p[i + 2][j + 2] * w22;
            // Submanifold mask: only write at active (nonzero-input) sites.
            o[i][j] = (p[i + 1][j + 1] != 0.0f) ? s : 0.0f;
        }
    }

    float4* yout = reinterpret_cast<float4*>(y) + (size_t)tile * 4;
    yout[0] = make_float4(o[0][0], o[0][1], o[0][2], o[0][3]);
    yout[1] = make_float4(o[1][0], o[1][1], o[1][2], o[1][3]);
    yout[2] = make_float4(o[2][0], o[2][1], o[2][2], o[2][3]);
    yout[3] = make_float4(o[3][0], o[3][1], o[3][2], o[3][3]);
}

extern "C" void kernel_launch(void* const* d_in, const int* in_sizes, int n_in,
                              void* d_out, int out_size)
{
    const float* x = (const float*)d_in[0];
    const float* W = (const float*)d_in[1];
    float* y = (float*)d_out;

    int n_tiles = in_sizes[0] / 16;  // 16 floats per 4x4x1 tile
    int threads = 256;
    int blocks = (n_tiles + threads - 1) / threads;
    subm_conv_tile_kernel<<<blocks, threads>>>(x, W, y, n_tiles);
}

// round 2
// speedup vs baseline: 1.0501x; 1.0501x over previous
#include <cuda_runtime.h>

// Submanifold 3x3 conv (cross-correlation, SAME) on independent 4x4x1 tiles.
// One thread per tile ROW (float4). Neighbor rows come from warp shuffles:
// tiles are 4 consecutive rows, 4 | 32 so a tile never straddles a warp.
// All global loads/stores are fully coalesced 128-bit accesses.

__global__ __launch_bounds__(256) void subm_conv_row_kernel(
    const float4* __restrict__ x,
    const float* __restrict__ W,
    float4* __restrict__ y,
    int n_vec)
{
    __shared__ float sw[9];
    if (threadIdx.x < 9) sw[threadIdx.x] = W[threadIdx.x];
    __syncthreads();

    int gid = blockIdx.x * blockDim.x + threadIdx.x;
    if (gid >= n_vec) return;

    float4 r = x[gid];                 // my row of the tile
    int rowid = gid & 3;               // row index within the 4x4 tile

    // Rows above/below from adjacent lanes (same tile).
    float4 a, b;
    a.x = __shfl_up_sync(0xffffffffu, r.x, 1);
    a.y = __shfl_up_sync(0xffffffffu, r.y, 1);
    a.z = __shfl_up_sync(0xffffffffu, r.z, 1);
    a.w = __shfl_up_sync(0xffffffffu, r.w, 1);
    b.x = __shfl_down_sync(0xffffffffu, r.x, 1);
    b.y = __shfl_down_sync(0xffffffffu, r.y, 1);
    b.z = __shfl_down_sync(0xffffffffu, r.z, 1);
    b.w = __shfl_down_sync(0xffffffffu, r.w, 1);
    if (rowid == 0) { a.x = a.y = a.z = a.w = 0.0f; }  // top tile edge
    if (rowid == 3) { b.x = b.y = b.z = b.w = 0.0f; }  // bottom tile edge

    // Zero-padded 6-wide rows; pad zeros constant-fold after unroll.
    float up[6]  = {0.0f, a.x, a.y, a.z, a.w, 0.0f};
    float mid[6] = {0.0f, r.x, r.y, r.z, r.w, 0.0f};
    float dn[6]  = {0.0f, b.x, b.y, b.z, b.w, 0.0f};

    float w00 = sw[0], w01 = sw[1], w02 = sw[2];
    float w10 = sw[3], w11 = sw[4], w12 = sw[5];
    float w20 = sw[6], w21 = sw[7], w22 = sw[8];

    float o[4];
#pragma unroll
    for (int j = 0; j < 4; j++) {
        float s = 0.0f;
        s += up[j + 0]  * w00;
        s += up[j + 1]  * w01;
        s += up[j + 2]  * w02;
        s += mid[j + 0] * w10;
        s += mid[j + 1] * w11;
        s += mid[j + 2] * w12;
        s += dn[j + 0]  * w20;
        s += dn[j + 1]  * w21;
        s += dn[j + 2]  * w22;
        // Submanifold mask: write only where the input site is nonzero.
        o[j] = (mid[j + 1] != 0.0f) ? s : 0.0f;
    }

    y[gid] = make_float4(o[0], o[1], o[2], o[3]);
}

extern "C" void kernel_launch(void* const* d_in, const int* in_sizes, int n_in,
                              void* d_out, int out_size)
{
    const float4* x = (const float4*)d_in[0];
    const float* W = (const float*)d_in[1];
    float4* y = (float4*)d_out;

    int n_vec = in_sizes[0] / 4;       // one float4 (tile row) per thread
    int threads = 256;
    int blocks = (n_vec + threads - 1) / threads;
    subm_conv_row_kernel<<<blocks, threads>>>(x, W, y, n_vec);
}

// round 3
// speedup vs baseline: 1.1110x; 1.0580x over previous
#include <cuda_runtime.h>

// Submanifold 3x3 conv (cross-correlation, SAME) on independent 4x4x1 tiles.
// One thread per ROW-PAIR (2x float4 = 32B). Tile = 2 pairs; 2 | 32 so a tile
// never straddles a warp. Inter-pair neighbor rows via 8 warp shuffles per
// thread (half of the per-byte shuffle cost of one-row-per-thread).

__global__ __launch_bounds__(256) void subm_conv_pair_kernel(
    const float4* __restrict__ x,
    const float* __restrict__ W,
    float4* __restrict__ y,
    int n_pairs)
{
    __shared__ float sw[9];
    if (threadIdx.x < 9) sw[threadIdx.x] = W[threadIdx.x];
    __syncthreads();

    int gid = blockIdx.x * blockDim.x + threadIdx.x;
    if (gid >= n_pairs) return;

    // Two consecutive tile rows (rows 2p, 2p+1 of the tile; p = gid & 1).
    float4 r0 = x[2 * (size_t)gid + 0];
    float4 r1 = x[2 * (size_t)gid + 1];
    int p = gid & 1;

    // Row above r0 comes from the previous lane's r1; row below r1 from the
    // next lane's r0. Zero at tile edges.
    float4 a, b;
    a.x = __shfl_up_sync(0xffffffffu, r1.x, 1);
    a.y = __shfl_up_sync(0xffffffffu, r1.y, 1);
    a.z = __shfl_up_sync(0xffffffffu, r1.z, 1);
    a.w = __shfl_up_sync(0xffffffffu, r1.w, 1);
    b.x = __shfl_down_sync(0xffffffffu, r0.x, 1);
    b.y = __shfl_down_sync(0xffffffffu, r0.y, 1);
    b.z = __shfl_down_sync(0xffffffffu, r0.z, 1);
    b.w = __shfl_down_sync(0xffffffffu, r0.w, 1);
    if (p == 0) { a.x = a.y = a.z = a.w = 0.0f; }  // top tile edge
    if (p == 1) { b.x = b.y = b.z = b.w = 0.0f; }  // bottom tile edge

    // Zero-padded 6-wide rows (pad zeros constant-fold after unroll).
    float ra[6] = {0.0f, a.x,  a.y,  a.z,  a.w,  0.0f};
    float rm[6] = {0.0f, r0.x, r0.y, r0.z, r0.w, 0.0f};
    float rn[6] = {0.0f, r1.x, r1.y, r1.z, r1.w, 0.0f};
    float rb[6] = {0.0f, b.x,  b.y,  b.z,  b.w,  0.0f};

    float w00 = sw[0], w01 = sw[1], w02 = sw[2];
    float w10 = sw[3], w11 = sw[4], w12 = sw[5];
    float w20 = sw[6], w21 = sw[7], w22 = sw[8];

    float o0[4], o1[4];
#pragma unroll
    for (int j = 0; j < 4; j++) {
        // Output row 2p: inputs (ra, rm, rn)
        float s0 = 0.0f;
        s0 += ra[j + 0] * w00;
        s0 += ra[j + 1] * w01;
        s0 += ra[j + 2] * w02;
        s0 += rm[j + 0] * w10;
        s0 += rm[j + 1] * w11;
        s0 += rm[j + 2] * w12;
        s0 += rn[j + 0] * w20;
        s0 += rn[j + 1] * w21;
        s0 += rn[j + 2] * w22;
        o0[j] = (rm[j + 1] != 0.0f) ? s0 : 0.0f;

        // Output row 2p+1: inputs (rm, rn, rb)
        float s1 = 0.0f;
        s1 += rm[j + 0] * w00;
        s1 += rm[j + 1] * w01;
        s1 += rm[j + 2] * w02;
        s1 += rn[j + 0] * w10;
        s1 += rn[j + 1] * w11;
        s1 += rn[j + 2] * w12;
        s1 += rb[j + 0] * w20;
        s1 += rb[j + 1] * w21;
        s1 += rb[j + 2] * w22;
        o1[j] = (rn[j + 1] != 0.0f) ? s1 : 0.0f;
    }

    y[2 * (size_t)gid + 0] = make_float4(o0[0], o0[1], o0[2], o0[3]);
    y[2 * (size_t)gid + 1] = make_float4(o1[0], o1[1], o1[2], o1[3]);
}

extern "C" void kernel_launch(void* const* d_in, const int* in_sizes, int n_in,
                              void* d_out, int out_size)
{
    const float4* x = (const float4*)d_in[0];
    const float* W = (const float*)d_in[1];
    float4* y = (float4*)d_out;

    int n_pairs = in_sizes[0] / 8;     // one thread per 8 floats (2 rows)
    int threads = 256;
    int blocks = (n_pairs + threads - 1) / threads;
    subm_conv_pair_kernel<<<blocks, threads>>>(x, W, y, n_pairs);
}

// round 4
// speedup vs baseline: 1.1263x; 1.0138x over previous
#include <cuda_runtime.h>

// Submanifold 3x3 conv (cross-correlation, SAME) on independent 4x4x1 tiles.
// One thread per ROW-PAIR (2x float4 = 32B). A 4x4 tile = 2 adjacent threads
// (p = gid & 1). Each thread needs exactly ONE row from its partner:
//   p=0 needs partner's r0 (row below its pair); its row-above is the tile
//       top edge (zero).
//   p=1 needs partner's r1 (row above its pair); its row-below is the tile
//       bottom edge (zero).
// One butterfly exchange (shfl.xor lane^1) moves both: each lane sends
// (p==0 ? r1 : r0). 4 SHFLs/thread instead of 8.

__global__ __launch_bounds__(256) void subm_conv_pair_kernel(
    const float4* __restrict__ x,
    const float* __restrict__ W,
    float4* __restrict__ y,
    int n_pairs)
{
    __shared__ float sw[9];
    if (threadIdx.x < 9) sw[threadIdx.x] = W[threadIdx.x];
    __syncthreads();

    int gid = blockIdx.x * blockDim.x + threadIdx.x;
    if (gid >= n_pairs) return;

    // Two consecutive tile rows (streaming loads: no reuse, evict-first).
    const float4* xin = x + 2 * (size_t)gid;
    float4 r0 = __ldcs(xin + 0);
    float4 r1 = __ldcs(xin + 1);
    int p = gid & 1;
    bool top = (p == 0);

    // Butterfly exchange with the partner lane (lane ^ 1, same tile).
    float4 send = top ? r1 : r0;      // the row my partner needs
    float4 recv;
    recv.x = __shfl_xor_sync(0xffffffffu, send.x, 1);
    recv.y = __shfl_xor_sync(0xffffffffu, send.y, 1);
    recv.z = __shfl_xor_sync(0xffffffffu, send.z, 1);
    recv.w = __shfl_xor_sync(0xffffffffu, send.w, 1);

    // a = row above r0 (zero at tile top); b = row below r1 (zero at bottom).
    float4 zero4 = make_float4(0.f, 0.f, 0.f, 0.f);
    float4 a = top ? zero4 : recv;
    float4 b = top ? recv : zero4;

    // Zero-padded 6-wide rows (pad zeros constant-fold after unroll).
    float ra[6] = {0.0f, a.x,  a.y,  a.z,  a.w,  0.0f};
    float rm[6] = {0.0f, r0.x, r0.y, r0.z, r0.w, 0.0f};
    float rn[6] = {0.0f, r1.x, r1.y, r1.z, r1.w, 0.0f};
    float rb[6] = {0.0f, b.x,  b.y,  b.z,  b.w,  0.0f};

    float w00 = sw[0], w01 = sw[1], w02 = sw[2];
    float w10 = sw[3], w11 = sw[4], w12 = sw[5];
    float w20 = sw[6], w21 = sw[7], w22 = sw[8];

    float o0[4], o1[4];
#pragma unroll
    for (int j = 0; j < 4; j++) {
        // Output for row r0: inputs (ra, rm, rn)
        float s0 = 0.0f;
        s0 += ra[j + 0] * w00;
        s0 += ra[j + 1] * w01;
        s0 += ra[j + 2] * w02;
        s0 += rm[j + 0] * w10;
        s0 += rm[j + 1] * w11;
        s0 += rm[j + 2] * w12;
        s0 += rn[j + 0] * w20;
        s0 += rn[j + 1] * w21;
        s0 += rn[j + 2] * w22;
        o0[j] = (rm[j + 1] != 0.0f) ? s0 : 0.0f;

        // Output for row r1: inputs (rm, rn, rb)
        float s1 = 0.0f;
        s1 += rm[j + 0] * w00;
        s1 += rm[j + 1] * w01;
        s1 += rm[j + 2] * w02;
        s1 += rn[j + 0] * w10;
        s1 += rn[j + 1] * w11;
        s1 += rn[j + 2] * w12;
        s1 += rb[j + 0] * w20;
        s1 += rb[j + 1] * w21;
        s1 += rb[j + 2] * w22;
        o1[j] = (rn[j + 1] != 0.0f) ? s1 : 0.0f;
    }

    // Streaming stores (no reuse).
    float4* yout = y + 2 * (size_t)gid;
    __stcs(yout + 0, make_float4(o0[0], o0[1], o0[2], o0[3]));
    __stcs(yout + 1, make_float4(o1[0], o1[1], o1[2], o1[3]));
}

extern "C" void kernel_launch(void* const* d_in, const int* in_sizes, int n_in,
                              void* d_out, int out_size)
{
    const float4* x = (const float4*)d_in[0];
    const float* W = (const float*)d_in[1];
    float4* y = (float4*)d_out;

    int n_pairs = in_sizes[0] / 8;     // one thread per 8 floats (2 rows)
    int threads = 256;
    int blocks = (n_pairs + threads - 1) / threads;
    subm_conv_pair_kernel<<<blocks, threads>>>(x, W, y, n_pairs);
}